// round 3
// baseline (speedup 1.0000x reference)
#include <cuda_runtime.h>
#include <math.h>

// Problem constants
#define B_   8
#define P_   16384
#define M_   16
#define CI_  16
#define CO_  32
#define W_   17
#define WSLOT 18          // 17 conv w-slots + 1 residual slot
#define OSTRIDE 288       // WSLOT*16 floats per output row in Wf
#define WWS  20           // padded per-m stride for ww

// smem (floats):
//   Wf   [32][288]  = 9216   (Wf[o][w*16+i], slot w=17 -> weight_res[o][i])
//   per-warp (4 warps), 336 floats each: ww [16][20] + nb [16]
// total = 9216 + 4*336 = 10560 floats = 42240 bytes

__global__ void __launch_bounds__(128, 4)
fused_conv_kernel(const float* __restrict__ in_pc,
                  const float* __restrict__ weights,
                  const float* __restrict__ bias,
                  const float* __restrict__ w_weights,
                  const float* __restrict__ weight_res,
                  const int*   __restrict__ neighbor_id,
                  float*       __restrict__ out)
{
    constexpr float SQ_CONV = 0.70710678118654752440f;
    constexpr float SQ_RES  = 0.70710678118654752440f;

    extern __shared__ float sm[];
    float* Wf = sm;                                   // [32][288]

    const int tid  = threadIdx.x;
    const int warp = tid >> 5;
    const int lane = tid & 31;

    float* ww_s = sm + 32 * OSTRIDE + warp * 336;     // [16][20]
    int*   nb_s = (int*)(ww_s + 320);                 // [16]

    // ---- stage weights: Wf[o][w*16+i], slot w=17 holds weight_res ----
    for (int idx = tid; idx < W_ * 512; idx += 128) {
        int w   = idx >> 9;
        int rem = idx & 511;
        int o   = rem >> 4;
        int i   = rem & 15;
        Wf[o * OSTRIDE + w * 16 + i] = weights[idx];
    }
    for (int idx = tid; idx < 512; idx += 128) {
        int o = idx >> 4, i = idx & 15;
        Wf[o * OSTRIDE + 272 + i] = weight_res[idx];
    }

    const int p = blockIdx.x * 4 + warp;

    // ---- per-warp staging: neighbor ids, masked ww ----
    if (lane < 16) nb_s[lane] = neighbor_id[p * M_ + lane];
    __syncwarp();
    for (int idx = lane; idx < 272; idx += 32) {
        int m = idx / 17;
        int w = idx - m * 17;
        float v = w_weights[(size_t)p * 272 + idx];
        ww_s[m * WWS + w] = (nb_s[m] == P_) ? 0.0f : v;
    }
    __syncthreads();

    const int b  = lane >> 2;
    const int ig = lane & 3;

    // gacc[w][j]: conv accumulators for this lane's i-chunk (w=0..16),
    // gacc[17] = own x chunk (residual input).
    float gacc[WSLOT][4];
    #pragma unroll
    for (int w = 0; w < 17; w++) {
        gacc[w][0] = 0.f; gacc[w][1] = 0.f; gacc[w][2] = 0.f; gacc[w][3] = 0.f;
    }
    {
        float4 xo = *(const float4*)&in_pc[((size_t)b * P_ + p) * CI_ + ig * 4];
        gacc[17][0] = xo.x; gacc[17][1] = xo.y; gacc[17][2] = xo.z; gacc[17][3] = xo.w;
    }

    // ---- stage A: g[w][chunk] = sum_m ww[m][w] * x[b, nb(m), chunk] ----
    const float* xbase = in_pc + (size_t)b * P_ * CI_ + ig * 4;
    #pragma unroll 4
    for (int m = 0; m < M_; m++) {
        int nb  = nb_s[m];
        int nbc = (nb == P_) ? 0 : nb;      // ww already zeroed for pad
        float4 x4 = *(const float4*)(xbase + (size_t)nbc * CI_);
        const float* wwm = ww_s + m * WWS;
        #pragma unroll
        for (int wg = 0; wg < 4; wg++) {
            float4 wv = *(const float4*)(wwm + wg * 4);
            gacc[wg*4+0][0] += wv.x * x4.x; gacc[wg*4+0][1] += wv.x * x4.y;
            gacc[wg*4+0][2] += wv.x * x4.z; gacc[wg*4+0][3] += wv.x * x4.w;
            gacc[wg*4+1][0] += wv.y * x4.x; gacc[wg*4+1][1] += wv.y * x4.y;
            gacc[wg*4+1][2] += wv.y * x4.z; gacc[wg*4+1][3] += wv.y * x4.w;
            gacc[wg*4+2][0] += wv.z * x4.x; gacc[wg*4+2][1] += wv.z * x4.y;
            gacc[wg*4+2][2] += wv.z * x4.z; gacc[wg*4+2][3] += wv.z * x4.w;
            gacc[wg*4+3][0] += wv.w * x4.x; gacc[wg*4+3][1] += wv.w * x4.y;
            gacc[wg*4+3][2] += wv.w * x4.z; gacc[wg*4+3][3] += wv.w * x4.w;
        }
        float w16 = wwm[16];
        gacc[16][0] += w16 * x4.x; gacc[16][1] += w16 * x4.y;
        gacc[16][2] += w16 * x4.z; gacc[16][3] += w16 * x4.w;
    }

    // ---- stage B: each lane computes partials (its k-chunk) for ALL o;
    //      cross-ig butterfly completes the dot; owning ig-lane writes octet.
    //      LDS address for (o,w): Wf + o*OSTRIDE + w*16 + ig*4
    //      -> 4 consecutive 16B chunks in ONE 128B line -> 1 wavefront/LDS.
    const float* wfcol = Wf + ig * 4;

    #pragma unroll 1
    for (int og = 0; og < 4; og++) {
        const float* wfb = wfcol + og * 8 * OSTRIDE;

        float acc[8], racc[8];
        #pragma unroll
        for (int oo = 0; oo < 8; oo++) { acc[oo] = 0.f; racc[oo] = 0.f; }

        #pragma unroll
        for (int w = 0; w < 17; w++) {
            #pragma unroll
            for (int oo = 0; oo < 8; oo++) {
                float4 wv = *(const float4*)(wfb + oo * OSTRIDE + w * 16);
                acc[oo] += wv.x * gacc[w][0] + wv.y * gacc[w][1]
                         + wv.z * gacc[w][2] + wv.w * gacc[w][3];
            }
        }
        #pragma unroll
        for (int oo = 0; oo < 8; oo++) {
            float4 wv = *(const float4*)(wfb + oo * OSTRIDE + 272);
            racc[oo] = wv.x * gacc[17][0] + wv.y * gacc[17][1]
                     + wv.z * gacc[17][2] + wv.w * gacc[17][3];
        }

        // butterfly over the ig-quad (lane bits 0-1)
        #pragma unroll
        for (int oo = 0; oo < 8; oo++) {
            acc[oo]  += __shfl_xor_sync(0xffffffffu, acc[oo],  1);
            acc[oo]  += __shfl_xor_sync(0xffffffffu, acc[oo],  2);
            racc[oo] += __shfl_xor_sync(0xffffffffu, racc[oo], 1);
            racc[oo] += __shfl_xor_sync(0xffffffffu, racc[oo], 2);
        }

        if (ig == og) {
            const int obase = og * 8;
            const float* bptr = bias + (size_t)p * CO_ + obase;
            float4 bz0 = *(const float4*)(bptr);
            float4 bz1 = *(const float4*)(bptr + 4);
            float bb[8] = {bz0.x, bz0.y, bz0.z, bz0.w, bz1.x, bz1.y, bz1.z, bz1.w};

            float res[8];
            #pragma unroll
            for (int oo = 0; oo < 8; oo++) {
                float c = acc[oo] + bb[oo];
                float e = (c > 0.0f) ? c : expm1f(c);
                res[oo] = e * SQ_CONV + racc[oo] * SQ_RES;
            }
            float* optr = out + ((size_t)b * P_ + p) * CO_ + obase;
            *(float4*)(optr)     = make_float4(res[0], res[1], res[2], res[3]);
            *(float4*)(optr + 4) = make_float4(res[4], res[5], res[6], res[7]);
        }
    }
}

extern "C" void kernel_launch(void* const* d_in, const int* in_sizes, int n_in,
                              void* d_out, int out_size)
{
    const float* in_pc       = nullptr;
    const float* weights     = nullptr;
    const float* bias        = nullptr;
    const float* w_weights   = nullptr;
    const float* weight_res  = nullptr;
    const int*   neighbor_id = nullptr;

    for (int i = 0; i < n_in; i++) {
        switch (in_sizes[i]) {
            case 2097152: in_pc       = (const float*)d_in[i]; break; // (8,16384,16)
            case 8704:    weights     = (const float*)d_in[i]; break; // (17,512)
            case 524288:  bias        = (const float*)d_in[i]; break; // (16384,32)
            case 4456448: w_weights   = (const float*)d_in[i]; break; // (16384,16,17)
            case 512:     weight_res  = (const float*)d_in[i]; break; // (32,16)
            case 262144:  neighbor_id = (const int*)d_in[i];   break; // (16384,16)
            default: break;
        }
    }

    const int smem_bytes = 10560 * 4; // 42240
    cudaFuncSetAttribute(fused_conv_kernel,
                         cudaFuncAttributeMaxDynamicSharedMemorySize, smem_bytes);

    fused_conv_kernel<<<P_ / 4, 128, smem_bytes>>>(
        in_pc, weights, bias, w_weights, weight_res, neighbor_id, (float*)d_out);
}

// round 4
// speedup vs baseline: 1.4182x; 1.4182x over previous
#include <cuda_runtime.h>
#include <math.h>

// Problem constants
#define B_   8
#define P_   16384
#define M_   16
#define CI_  16
#define CO_  32
#define W_   17
#define WSLOT 18          // 17 conv w-slots + 1 residual slot
#define OSTRIDE 288       // WSLOT*16 floats per output row in Wf
#define WWS  20           // padded per-m stride for ww

// smem (floats):
//   Wf   [32][288]  = 9216   (Wf[o][w*16+i], slot w=17 -> weight_res[o][i])
//   per-warp (4 warps), 336 floats each: ww [16][20] + nb [16]
// total = 9216 + 4*336 = 10560 floats = 42240 bytes

__global__ void __launch_bounds__(128, 4)
fused_conv_kernel(const float* __restrict__ in_pc,
                  const float* __restrict__ weights,
                  const float* __restrict__ bias,
                  const float* __restrict__ w_weights,
                  const float* __restrict__ weight_res,
                  const int*   __restrict__ neighbor_id,
                  float*       __restrict__ out)
{
    constexpr float SQ_CONV = 0.70710678118654752440f;
    constexpr float SQ_RES  = 0.70710678118654752440f;

    extern __shared__ float sm[];
    float* Wf = sm;                                   // [32][288]

    const int tid  = threadIdx.x;
    const int warp = tid >> 5;
    const int lane = tid & 31;

    float* ww_s = sm + 32 * OSTRIDE + warp * 336;     // [16][20]
    int*   nb_s = (int*)(ww_s + 320);                 // [16]

    // ---- stage weights: Wf[o][w*16+i], slot w=17 holds weight_res ----
    for (int idx = tid; idx < W_ * 512; idx += 128) {
        int w   = idx >> 9;
        int rem = idx & 511;
        int o   = rem >> 4;
        int i   = rem & 15;
        Wf[o * OSTRIDE + w * 16 + i] = weights[idx];
    }
    for (int idx = tid; idx < 512; idx += 128) {
        int o = idx >> 4, i = idx & 15;
        Wf[o * OSTRIDE + 272 + i] = weight_res[idx];
    }

    const int p = blockIdx.x * 4 + warp;

    // ---- per-warp staging: neighbor ids, masked ww ----
    if (lane < 16) nb_s[lane] = neighbor_id[p * M_ + lane];
    __syncwarp();
    for (int idx = lane; idx < 272; idx += 32) {
        int m = idx / 17;
        int w = idx - m * 17;
        float v = w_weights[(size_t)p * 272 + idx];
        ww_s[m * WWS + w] = (nb_s[m] == P_) ? 0.0f : v;
    }
    __syncthreads();

    // lane ownership: bg = lane>>3 (0..3), ih = lane&7 (0..7)
    //   batches b_lo = bg, b_hi = bg+4 ; channels i = 2*ih, 2*ih+1 ; all w.
    const int bg = lane >> 3;
    const int ih = lane & 7;
    const int b_lo = bg;
    const int b_hi = bg + 4;

    // gacc[w][i'][b']: w=0..16 conv accumulators; slot 17 = own x (residual).
    float gacc[WSLOT][2][2];
    #pragma unroll
    for (int w = 0; w < 17; w++) {
        gacc[w][0][0] = 0.f; gacc[w][0][1] = 0.f;
        gacc[w][1][0] = 0.f; gacc[w][1][1] = 0.f;
    }
    {
        float2 xl = *(const float2*)&in_pc[((size_t)b_lo * P_ + p) * CI_ + 2 * ih];
        float2 xh = *(const float2*)&in_pc[((size_t)b_hi * P_ + p) * CI_ + 2 * ih];
        gacc[17][0][0] = xl.x; gacc[17][1][0] = xl.y;
        gacc[17][0][1] = xh.x; gacc[17][1][1] = xh.y;
    }

    // ---- stage A ----
    const float* xlo = in_pc + (size_t)b_lo * P_ * CI_ + 2 * ih;
    const float* xhi = in_pc + (size_t)b_hi * P_ * CI_ + 2 * ih;
    #pragma unroll 4
    for (int m = 0; m < M_; m++) {
        int nb  = nb_s[m];
        int nbc = (nb == P_) ? 0 : nb;          // ww zeroed for pad
        float2 xa = *(const float2*)(xlo + (size_t)nbc * CI_);
        float2 xc = *(const float2*)(xhi + (size_t)nbc * CI_);
        const float* wwm = ww_s + m * WWS;
        #pragma unroll
        for (int wg = 0; wg < 4; wg++) {
            float4 wv = *(const float4*)(wwm + wg * 4);
            float f0 = wv.x, f1 = wv.y, f2 = wv.z, f3 = wv.w;
            int w = wg * 4;
            gacc[w+0][0][0] += f0*xa.x; gacc[w+0][1][0] += f0*xa.y;
            gacc[w+0][0][1] += f0*xc.x; gacc[w+0][1][1] += f0*xc.y;
            gacc[w+1][0][0] += f1*xa.x; gacc[w+1][1][0] += f1*xa.y;
            gacc[w+1][0][1] += f1*xc.x; gacc[w+1][1][1] += f1*xc.y;
            gacc[w+2][0][0] += f2*xa.x; gacc[w+2][1][0] += f2*xa.y;
            gacc[w+2][0][1] += f2*xc.x; gacc[w+2][1][1] += f2*xc.y;
            gacc[w+3][0][0] += f3*xa.x; gacc[w+3][1][0] += f3*xa.y;
            gacc[w+3][0][1] += f3*xc.x; gacc[w+3][1][1] += f3*xc.y;
        }
        float f16 = wwm[16];
        gacc[16][0][0] += f16*xa.x; gacc[16][1][0] += f16*xa.y;
        gacc[16][0][1] += f16*xc.x; gacc[16][1][1] += f16*xc.y;
    }

    // ---- stage B: per o-group of 8, LDS.64 of Wf feeds 4 FMAs ----
    const float* wfih = Wf + 2 * ih;

    #pragma unroll 1
    for (int og = 0; og < 4; og++) {
        const float* wfo = wfih + og * 8 * OSTRIDE;

        float acc[8][2], racc[8][2];
        #pragma unroll
        for (int oo = 0; oo < 8; oo++) {
            acc[oo][0] = 0.f; acc[oo][1] = 0.f;
            racc[oo][0] = 0.f; racc[oo][1] = 0.f;
        }

        #pragma unroll
        for (int w = 0; w < 17; w++) {
            #pragma unroll
            for (int oo = 0; oo < 8; oo++) {
                float2 wv = *(const float2*)(wfo + oo * OSTRIDE + w * 16);
                acc[oo][0] += wv.x * gacc[w][0][0] + wv.y * gacc[w][1][0];
                acc[oo][1] += wv.x * gacc[w][0][1] + wv.y * gacc[w][1][1];
            }
        }
        #pragma unroll
        for (int oo = 0; oo < 8; oo++) {
            float2 wv = *(const float2*)(wfo + oo * OSTRIDE + 272);
            racc[oo][0] = wv.x * gacc[17][0][0] + wv.y * gacc[17][1][0];
            racc[oo][1] = wv.x * gacc[17][0][1] + wv.y * gacc[17][1][1];
        }

        // ---- reduce-scatter over the 8 ih lanes: lane ends with oo = ih ----
        float a2[4][2], r2[4][2];
        {
            const bool h = (ih & 4) != 0;
            #pragma unroll
            for (int t = 0; t < 4; t++) {
                #pragma unroll
                for (int j = 0; j < 2; j++) {
                    float ka = h ? acc[4+t][j]  : acc[t][j];
                    float sa = h ? acc[t][j]    : acc[4+t][j];
                    a2[t][j] = ka + __shfl_xor_sync(0xffffffffu, sa, 4);
                    float kr = h ? racc[4+t][j] : racc[t][j];
                    float sr = h ? racc[t][j]   : racc[4+t][j];
                    r2[t][j] = kr + __shfl_xor_sync(0xffffffffu, sr, 4);
                }
            }
        }
        float a1[2][2], r1[2][2];
        {
            const bool h = (ih & 2) != 0;
            #pragma unroll
            for (int t = 0; t < 2; t++) {
                #pragma unroll
                for (int j = 0; j < 2; j++) {
                    float ka = h ? a2[2+t][j] : a2[t][j];
                    float sa = h ? a2[t][j]   : a2[2+t][j];
                    a1[t][j] = ka + __shfl_xor_sync(0xffffffffu, sa, 2);
                    float kr = h ? r2[2+t][j] : r2[t][j];
                    float sr = h ? r2[t][j]   : r2[2+t][j];
                    r1[t][j] = kr + __shfl_xor_sync(0xffffffffu, sr, 2);
                }
            }
        }
        float a0[2], r0[2];
        {
            const bool h = (ih & 1) != 0;
            #pragma unroll
            for (int j = 0; j < 2; j++) {
                float ka = h ? a1[1][j] : a1[0][j];
                float sa = h ? a1[0][j] : a1[1][j];
                a0[j] = ka + __shfl_xor_sync(0xffffffffu, sa, 1);
                float kr = h ? r1[1][j] : r1[0][j];
                float sr = h ? r1[0][j] : r1[1][j];
                r0[j] = kr + __shfl_xor_sync(0xffffffffu, sr, 1);
            }
        }

        // ---- epilogue: lane writes o = og*8 + ih for its two batches ----
        const int o = og * 8 + ih;
        float bi = bias[(size_t)p * CO_ + o];

        float c0 = a0[0] + bi;
        float e0 = (c0 > 0.0f) ? c0 : expm1f(c0);
        out[((size_t)b_lo * P_ + p) * CO_ + o] = e0 * SQ_CONV + r0[0] * SQ_RES;

        float c1 = a0[1] + bi;
        float e1 = (c1 > 0.0f) ? c1 : expm1f(c1);
        out[((size_t)b_hi * P_ + p) * CO_ + o] = e1 * SQ_CONV + r0[1] * SQ_RES;
    }
}

extern "C" void kernel_launch(void* const* d_in, const int* in_sizes, int n_in,
                              void* d_out, int out_size)
{
    const float* in_pc       = nullptr;
    const float* weights     = nullptr;
    const float* bias        = nullptr;
    const float* w_weights   = nullptr;
    const float* weight_res  = nullptr;
    const int*   neighbor_id = nullptr;

    for (int i = 0; i < n_in; i++) {
        switch (in_sizes[i]) {
            case 2097152: in_pc       = (const float*)d_in[i]; break; // (8,16384,16)
            case 8704:    weights     = (const float*)d_in[i]; break; // (17,512)
            case 524288:  bias        = (const float*)d_in[i]; break; // (16384,32)
            case 4456448: w_weights   = (const float*)d_in[i]; break; // (16384,16,17)
            case 512:     weight_res  = (const float*)d_in[i]; break; // (32,16)
            case 262144:  neighbor_id = (const int*)d_in[i];   break; // (16384,16)
            default: break;
        }
    }

    const int smem_bytes = 10560 * 4; // 42240
    cudaFuncSetAttribute(fused_conv_kernel,
                         cudaFuncAttributeMaxDynamicSharedMemorySize, smem_bytes);

    fused_conv_kernel<<<P_ / 4, 128, smem_bytes>>>(
        in_pc, weights, bias, w_weights, weight_res, neighbor_id, (float*)d_out);
}

// round 5
// speedup vs baseline: 1.6097x; 1.1350x over previous
#include <cuda_runtime.h>
#include <math.h>
#include <stdint.h>

// Problem constants
#define B_   8
#define P_   16384
#define M_   16
#define CI_  16
#define CO_  32
#define W_   17
#define WSLOT 18          // 17 conv w-slots + 1 residual slot
#define OSTRIDE 288       // WSLOT*16 floats per output row in Wf
#define WWS  20           // padded per-m stride for ww

// packed f32x2 helpers (SASS FFMA2 path — only reachable via PTX)
#define FMA_F32X2(d, a, b, c) \
    asm("fma.rn.f32x2 %0, %1, %2, %3;" : "=l"(d) : "l"(a), "l"(b), "l"(c))
#define PACK_REPL_F32X2(out, s) \
    asm("mov.b64 %0, {%1, %1};" : "=l"(out) : "r"(s))
#define UNPACK_F32X2(lo, hi, in) \
    asm("mov.b64 {%0, %1}, %2;" : "=r"(lo), "=r"(hi) : "l"(in))

// smem (floats):
//   Wf   [32][288]  = 9216   (Wf[o][w*16+i], slot w=17 -> weight_res[o][i])
//   per-warp (4 warps), 336 floats each: ww [16][20] + nb [16]
// total = 9216 + 4*336 = 10560 floats = 42240 bytes

__global__ void __launch_bounds__(128, 4)
fused_conv_kernel(const float* __restrict__ in_pc,
                  const float* __restrict__ weights,
                  const float* __restrict__ bias,
                  const float* __restrict__ w_weights,
                  const float* __restrict__ weight_res,
                  const int*   __restrict__ neighbor_id,
                  float*       __restrict__ out)
{
    constexpr float SQ_CONV = 0.70710678118654752440f;
    constexpr float SQ_RES  = 0.70710678118654752440f;

    extern __shared__ float sm[];
    float* Wf = sm;                                   // [32][288]

    const int tid  = threadIdx.x;
    const int warp = tid >> 5;
    const int lane = tid & 31;

    float* ww_s = sm + 32 * OSTRIDE + warp * 336;     // [16][20]
    int*   nb_s = (int*)(ww_s + 320);                 // [16]

    // ---- stage weights: Wf[o][w*16+i], slot w=17 holds weight_res ----
    for (int idx = tid; idx < W_ * 512; idx += 128) {
        int w   = idx >> 9;
        int rem = idx & 511;
        int o   = rem >> 4;
        int i   = rem & 15;
        Wf[o * OSTRIDE + w * 16 + i] = weights[idx];
    }
    for (int idx = tid; idx < 512; idx += 128) {
        int o = idx >> 4, i = idx & 15;
        Wf[o * OSTRIDE + 272 + i] = weight_res[idx];
    }

    const int p = blockIdx.x * 4 + warp;

    // ---- per-warp staging: neighbor ids, masked ww ----
    if (lane < 16) nb_s[lane] = neighbor_id[p * M_ + lane];
    __syncwarp();
    for (int idx = lane; idx < 272; idx += 32) {
        int m = idx / 17;
        int w = idx - m * 17;
        float v = w_weights[(size_t)p * 272 + idx];
        ww_s[m * WWS + w] = (nb_s[m] == P_) ? 0.0f : v;
    }
    __syncthreads();

    // lane ownership: bg = lane>>3 (0..3), ih = lane&7 (0..7)
    //   batches b_lo = bg, b_hi = bg+4 ; channel pair i = 2ih, 2ih+1.
    const int bg = lane >> 3;
    const int ih = lane & 7;
    const int b_lo = bg;
    const int b_hi = bg + 4;

    // gacc2[w][b']: f32x2 packed over the channel pair. slot 17 = own x.
    unsigned long long gacc2[WSLOT][2];
    #pragma unroll
    for (int w = 0; w < 17; w++) { gacc2[w][0] = 0ull; gacc2[w][1] = 0ull; }
    {
        gacc2[17][0] = *(const unsigned long long*)&in_pc[((size_t)b_lo * P_ + p) * CI_ + 2 * ih];
        gacc2[17][1] = *(const unsigned long long*)&in_pc[((size_t)b_hi * P_ + p) * CI_ + 2 * ih];
    }

    // ---- stage A: packed over channels ----
    const float* xlo = in_pc + (size_t)b_lo * P_ * CI_ + 2 * ih;
    const float* xhi = in_pc + (size_t)b_hi * P_ * CI_ + 2 * ih;
    #pragma unroll 4
    for (int m = 0; m < M_; m++) {
        int nb  = nb_s[m];
        int nbc = (nb == P_) ? 0 : nb;          // ww zeroed for pad
        unsigned long long xa = *(const unsigned long long*)(xlo + (size_t)nbc * CI_);
        unsigned long long xc = *(const unsigned long long*)(xhi + (size_t)nbc * CI_);
        const float* wwm = ww_s + m * WWS;
        #pragma unroll
        for (int wg = 0; wg < 4; wg++) {
            float4 wv = *(const float4*)(wwm + wg * 4);
            int w = wg * 4;
            unsigned long long f2;
            uint32_t fb;
            fb = __float_as_uint(wv.x); PACK_REPL_F32X2(f2, fb);
            FMA_F32X2(gacc2[w+0][0], f2, xa, gacc2[w+0][0]);
            FMA_F32X2(gacc2[w+0][1], f2, xc, gacc2[w+0][1]);
            fb = __float_as_uint(wv.y); PACK_REPL_F32X2(f2, fb);
            FMA_F32X2(gacc2[w+1][0], f2, xa, gacc2[w+1][0]);
            FMA_F32X2(gacc2[w+1][1], f2, xc, gacc2[w+1][1]);
            fb = __float_as_uint(wv.z); PACK_REPL_F32X2(f2, fb);
            FMA_F32X2(gacc2[w+2][0], f2, xa, gacc2[w+2][0]);
            FMA_F32X2(gacc2[w+2][1], f2, xc, gacc2[w+2][1]);
            fb = __float_as_uint(wv.w); PACK_REPL_F32X2(f2, fb);
            FMA_F32X2(gacc2[w+3][0], f2, xa, gacc2[w+3][0]);
            FMA_F32X2(gacc2[w+3][1], f2, xc, gacc2[w+3][1]);
        }
        {
            uint32_t fb = __float_as_uint(wwm[16]);
            unsigned long long f2; PACK_REPL_F32X2(f2, fb);
            FMA_F32X2(gacc2[16][0], f2, xa, gacc2[16][0]);
            FMA_F32X2(gacc2[16][1], f2, xc, gacc2[16][1]);
        }
    }

    // unpack own-x (residual input) once
    float g17l0, g17l1, g17h0, g17h1;
    {
        uint32_t a0, a1;
        UNPACK_F32X2(a0, a1, gacc2[17][0]);
        g17l0 = __uint_as_float(a0); g17l1 = __uint_as_float(a1);
        UNPACK_F32X2(a0, a1, gacc2[17][1]);
        g17h0 = __uint_as_float(a0); g17h1 = __uint_as_float(a1);
    }

    // ---- stage B: packed FFMA2 on Wf LDS.64 (register-pair = packed operand) ----
    const float* wfih = Wf + 2 * ih;

    #pragma unroll 1
    for (int og = 0; og < 4; og++) {
        const float* wfo = wfih + og * 8 * OSTRIDE;

        unsigned long long acc2[8][2];
        #pragma unroll
        for (int oo = 0; oo < 8; oo++) { acc2[oo][0] = 0ull; acc2[oo][1] = 0ull; }

        #pragma unroll
        for (int w = 0; w < 17; w++) {
            #pragma unroll
            for (int oo = 0; oo < 8; oo++) {
                unsigned long long wv =
                    *(const unsigned long long*)(wfo + oo * OSTRIDE + w * 16);
                FMA_F32X2(acc2[oo][0], wv, gacc2[w][0], acc2[oo][0]);
                FMA_F32X2(acc2[oo][1], wv, gacc2[w][1], acc2[oo][1]);
            }
        }

        // horizontal add (channel pair) -> scalar partials
        float acc[8][2];
        #pragma unroll
        for (int oo = 0; oo < 8; oo++) {
            uint32_t l0, h0, l1, h1;
            UNPACK_F32X2(l0, h0, acc2[oo][0]);
            UNPACK_F32X2(l1, h1, acc2[oo][1]);
            acc[oo][0] = __uint_as_float(l0) + __uint_as_float(h0);
            acc[oo][1] = __uint_as_float(l1) + __uint_as_float(h1);
        }

        // residual partials (scalar; w-slot 17)
        float racc[8][2];
        #pragma unroll
        for (int oo = 0; oo < 8; oo++) {
            float2 wv = *(const float2*)(wfo + oo * OSTRIDE + 272);
            racc[oo][0] = wv.x * g17l0 + wv.y * g17l1;
            racc[oo][1] = wv.x * g17h0 + wv.y * g17h1;
        }

        // ---- reduce-scatter over the 8 ih lanes: lane ends with oo = ih ----
        float a2[4][2], r2[4][2];
        {
            const bool h = (ih & 4) != 0;
            #pragma unroll
            for (int t = 0; t < 4; t++) {
                #pragma unroll
                for (int j = 0; j < 2; j++) {
                    float ka = h ? acc[4+t][j]  : acc[t][j];
                    float sa = h ? acc[t][j]    : acc[4+t][j];
                    a2[t][j] = ka + __shfl_xor_sync(0xffffffffu, sa, 4);
                    float kr = h ? racc[4+t][j] : racc[t][j];
                    float sr = h ? racc[t][j]   : racc[4+t][j];
                    r2[t][j] = kr + __shfl_xor_sync(0xffffffffu, sr, 4);
                }
            }
        }
        float a1[2][2], r1[2][2];
        {
            const bool h = (ih & 2) != 0;
            #pragma unroll
            for (int t = 0; t < 2; t++) {
                #pragma unroll
                for (int j = 0; j < 2; j++) {
                    float ka = h ? a2[2+t][j] : a2[t][j];
                    float sa = h ? a2[t][j]   : a2[2+t][j];
                    a1[t][j] = ka + __shfl_xor_sync(0xffffffffu, sa, 2);
                    float kr = h ? r2[2+t][j] : r2[t][j];
                    float sr = h ? r2[t][j]   : r2[2+t][j];
                    r1[t][j] = kr + __shfl_xor_sync(0xffffffffu, sr, 2);
                }
            }
        }
        float a0[2], r0[2];
        {
            const bool h = (ih & 1) != 0;
            #pragma unroll
            for (int j = 0; j < 2; j++) {
                float ka = h ? a1[1][j] : a1[0][j];
                float sa = h ? a1[0][j] : a1[1][j];
                a0[j] = ka + __shfl_xor_sync(0xffffffffu, sa, 1);
                float kr = h ? r1[1][j] : r1[0][j];
                float sr = h ? r1[0][j] : r1[1][j];
                r0[j] = kr + __shfl_xor_sync(0xffffffffu, sr, 1);
            }
        }

        // ---- epilogue: lane writes o = og*8 + ih for its two batches ----
        const int o = og * 8 + ih;
        float bi = bias[(size_t)p * CO_ + o];

        float c0 = a0[0] + bi;
        float e0 = (c0 > 0.0f) ? c0 : expm1f(c0);
        out[((size_t)b_lo * P_ + p) * CO_ + o] = e0 * SQ_CONV + r0[0] * SQ_RES;

        float c1 = a0[1] + bi;
        float e1 = (c1 > 0.0f) ? c1 : expm1f(c1);
        out[((size_t)b_hi * P_ + p) * CO_ + o] = e1 * SQ_CONV + r0[1] * SQ_RES;
    }
}

extern "C" void kernel_launch(void* const* d_in, const int* in_sizes, int n_in,
                              void* d_out, int out_size)
{
    const float* in_pc       = nullptr;
    const float* weights     = nullptr;
    const float* bias        = nullptr;
    const float* w_weights   = nullptr;
    const float* weight_res  = nullptr;
    const int*   neighbor_id = nullptr;

    for (int i = 0; i < n_in; i++) {
        switch (in_sizes[i]) {
            case 2097152: in_pc       = (const float*)d_in[i]; break; // (8,16384,16)
            case 8704:    weights     = (const float*)d_in[i]; break; // (17,512)
            case 524288:  bias        = (const float*)d_in[i]; break; // (16384,32)
            case 4456448: w_weights   = (const float*)d_in[i]; break; // (16384,16,17)
            case 512:     weight_res  = (const float*)d_in[i]; break; // (32,16)
            case 262144:  neighbor_id = (const int*)d_in[i];   break; // (16384,16)
            default: break;
        }
    }

    const int smem_bytes = 10560 * 4; // 42240
    cudaFuncSetAttribute(fused_conv_kernel,
                         cudaFuncAttributeMaxDynamicSharedMemorySize, smem_bytes);

    fused_conv_kernel<<<P_ / 4, 128, smem_bytes>>>(
        in_pc, weights, bias, w_weights, weight_res, neighbor_id, (float*)d_out);
}